// round 2
// baseline (speedup 1.0000x reference)
#include <cuda_runtime.h>
#include <cuda_bf16.h>

#define N_COLS 2048                      // hidden dim
#define VECS_PER_ROW (N_COLS / 4)        // 512 float4
#define VECS_PER_LANE (VECS_PER_ROW / 32) // 16 float4 per lane
#define THREADS 128                      // 4 warps per CTA, 1 row per warp
#define WARPS_PER_CTA (THREADS / 32)
#define EPS 1e-5f

__global__ __launch_bounds__(THREADS)
void rmsnorm_kernel(const float4* __restrict__ x,
                    const float4* __restrict__ g,
                    float4* __restrict__ out)
{
    const int lane = threadIdx.x & 31;
    const int warp = threadIdx.x >> 5;
    const size_t row = (size_t)blockIdx.x * WARPS_PER_CTA + warp;

    const float4* xr = x + row * VECS_PER_ROW;
    float4* outr = out + row * VECS_PER_ROW;

    // 16 independent LDG.128 per lane, front-batched (MLP=16).
    // __ldcs: read-once streaming hint (evict-first in L2).
    float4 v[VECS_PER_LANE];
    #pragma unroll
    for (int i = 0; i < VECS_PER_LANE; i++)
        v[i] = __ldcs(&xr[lane + 32 * i]);

    // Sum of squares with 4 independent accumulator chains.
    float a0 = 0.f, a1 = 0.f, a2 = 0.f, a3 = 0.f;
    #pragma unroll
    for (int i = 0; i < VECS_PER_LANE; i += 4) {
        a0 += v[i+0].x * v[i+0].x + v[i+0].y * v[i+0].y + v[i+0].z * v[i+0].z + v[i+0].w * v[i+0].w;
        a1 += v[i+1].x * v[i+1].x + v[i+1].y * v[i+1].y + v[i+1].z * v[i+1].z + v[i+1].w * v[i+1].w;
        a2 += v[i+2].x * v[i+2].x + v[i+2].y * v[i+2].y + v[i+2].z * v[i+2].z + v[i+2].w * v[i+2].w;
        a3 += v[i+3].x * v[i+3].x + v[i+3].y * v[i+3].y + v[i+3].z * v[i+3].z + v[i+3].w * v[i+3].w;
    }
    float ss = (a0 + a1) + (a2 + a3);

    // Warp-only reduce (xor tree leaves the full sum in every lane). No barriers.
    #pragma unroll
    for (int off = 16; off > 0; off >>= 1)
        ss += __shfl_xor_sync(0xFFFFFFFFu, ss, off);

    const float scale = rsqrtf(ss * (1.0f / (float)N_COLS) + EPS);

    // Scale by g (L1/L2-resident, 8 KB) and stream out (STG.128, evict-first).
    #pragma unroll
    for (int i = 0; i < VECS_PER_LANE; i++) {
        float4 gv = g[lane + 32 * i];
        float4 o;
        o.x = v[i].x * scale * gv.x;
        o.y = v[i].y * scale * gv.y;
        o.z = v[i].z * scale * gv.z;
        o.w = v[i].w * scale * gv.w;
        __stcs(&outr[lane + 32 * i], o);
    }
}

extern "C" void kernel_launch(void* const* d_in, const int* in_sizes, int n_in,
                              void* d_out, int out_size)
{
    const float4* x = (const float4*)d_in[0];
    const float4* g = (const float4*)d_in[1];
    float4* out = (float4*)d_out;

    const int n_rows = in_sizes[0] / N_COLS;          // 16384
    const int n_blocks = n_rows / WARPS_PER_CTA;      // 4096

    rmsnorm_kernel<<<n_blocks, THREADS>>>(x, g, out);
}